// round 12
// baseline (speedup 1.0000x reference)
#include <cuda_runtime.h>
#include <cuda_bf16.h>
#include <cuda_fp16.h>
#include <cstdint>
#include <math.h>

#define BB 8
#define NN 2048
#define FI 128
#define FO 64
#define KT 64
#define TI 64
#define NCHUNK (NN / KT)

#define WH_BLOCKS (BB * NN / 128)     // 128
#define MASK_BLOCKS 896
#define MASK_WARPS (MASK_BLOCKS * 8)
#define RC (BB * NN * NCHUNK)         // 524288 row-chunks

// ---------------- scratch (static device arrays: allocation-free) ----------
__device__ __half g_Wh_h[(size_t)BB * NN * FO];     // [row][f] 2MB, fp16
__device__ uint4 g_srowP[BB * NN];       // (h2(-s1,-s1), h2(E1,E1), h2(F1,F1), 0)
__device__ uint4 g_scolP[BB * NN / 2];   // per j-pair: (h2(s2,s2'), h2(E2,E2'), h2(F2,F2'), 0)
__device__ uint2 g_adjbits[RC];          // per (row, chunk): (even-j bits, odd-j bits) 4MB

// ---------------- helpers ---------------------------------------------------
__device__ __forceinline__ uint32_t smem_u32(const void* p) {
    uint32_t a;
    asm("{ .reg .u64 t; cvta.to.shared.u64 t, %1; cvt.u32.u64 %0, t; }" : "=r"(a) : "l"(p));
    return a;
}

__device__ __forceinline__ void mma16816(float* c, uint32_t a0, uint32_t a1,
                                         uint32_t a2, uint32_t a3,
                                         uint32_t b0, uint32_t b1) {
    asm volatile("mma.sync.aligned.m16n8k16.row.col.f32.f16.f16.f32 "
                 "{%0,%1,%2,%3}, {%4,%5,%6,%7}, {%8,%9}, {%0,%1,%2,%3};"
                 : "+f"(c[0]), "+f"(c[1]), "+f"(c[2]), "+f"(c[3])
                 : "r"(a0), "r"(a1), "r"(a2), "r"(a3), "r"(b0), "r"(b1));
}

__device__ __forceinline__ void ldsm4t(uint32_t* r, uint32_t addr) {
    asm volatile("ldmatrix.sync.aligned.m8n8.x4.trans.shared.b16 {%0,%1,%2,%3}, [%4];"
                 : "=r"(r[0]), "=r"(r[1]), "=r"(r[2]), "=r"(r[3]) : "r"(addr));
}

__device__ __forceinline__ void ldsm2t(uint32_t* r, uint32_t addr) {
    asm volatile("ldmatrix.sync.aligned.m8n8.x2.trans.shared.b16 {%0,%1}, [%2];"
                 : "=r"(r[0]), "=r"(r[1]) : "r"(addr));
}

__device__ __forceinline__ void cpasync16(uint32_t dst, const void* src) {
    asm volatile("cp.async.ca.shared.global [%0], [%1], 16;" :: "r"(dst), "l"(src));
}

__device__ __forceinline__ uint32_t h2u(float x, float y) {
    __half2 v = __float22half2_rn(make_float2(x, y));
    return *(uint32_t*)&v;
}

// per-half-lane 0xFFFF mask where a > b (fp16x2 compare)
__device__ __forceinline__ uint32_t setgt2(uint32_t a, uint32_t b) {
    uint32_t m;
    asm("set.gt.u32.f16x2 %0, %1, %2;" : "=r"(m) : "r"(a), "r"(b));
    return m;
}

__device__ __forceinline__ uint32_t hmul2u(uint32_t a, uint32_t b) {
    uint32_t d;
    asm("mul.f16x2 %0, %1, %2;" : "=r"(d) : "r"(a), "r"(b));
    return d;
}

// bit-select: (x & m) | (y & ~m)   -> single LOP3
__device__ __forceinline__ uint32_t bsel(uint32_t x, uint32_t y, uint32_t m) {
    return (x & m) | (y & ~m);
}

// (evenbits, oddbits) -> packed halfword mask for pair index k
__device__ __forceinline__ uint32_t pairmask(uint2 m, int k) {
    return (((m.x >> k) & 1u) + (((m.y >> k) & 1u) << 16)) * 0xFFFFu;
}

__device__ __forceinline__ float f4c(const float4& v, int k) {
    return k == 0 ? v.x : (k == 1 ? v.y : (k == 2 ? v.z : v.w));
}

// ---------------------------------------------------------------------------
// Kernel A: blocks [0,128): Wh = h @ W + packed attention tables.
//           blocks [128, 128+896): adj -> bitmask compression (concurrent).
// ---------------------------------------------------------------------------
__global__ void __launch_bounds__(256, 2) wh_mask_kernel(const float* __restrict__ h,
                                                         const float* __restrict__ W,
                                                         const float* __restrict__ a,
                                                         const int* __restrict__ adj) {
    if (blockIdx.x >= WH_BLOCKS) {
        // ---------------- mask compression blocks ----------------
        const int lane = threadIdx.x & 31;
        const int gw = (blockIdx.x - WH_BLOCKS) * 8 + (threadIdx.x >> 5);
        for (int base = gw * 4; base < RC; base += MASK_WARPS * 4) {
            int2 v[4];
            #pragma unroll
            for (int u = 0; u < 4; ++u)
                v[u] = *(const int2*)(adj + (size_t)(base + u) * KT + lane * 2);
            #pragma unroll
            for (int u = 0; u < 4; ++u) {
                const uint32_t evn = __ballot_sync(0xffffffffu, v[u].x);
                const uint32_t odd = __ballot_sync(0xffffffffu, v[u].y);
                if (lane == 0) g_adjbits[base + u] = make_uint2(evn, odd);
            }
        }
        return;
    }

    // ---------------- Wh blocks (proven R10 body) ----------------
    extern __shared__ __align__(16) unsigned char smem_raw[];
    float4* sh4 = (float4*)smem_raw;                     // 128 x 128 f32 = 64KB
    float4* sW4 = (float4*)(smem_raw + 65536);           // 128 x 64 f32 = 32KB

    const int tid  = threadIdx.x;
    const int row0 = blockIdx.x * 128;

    const float4* hsrc = (const float4*)(h + (size_t)row0 * FI);
    #pragma unroll 4
    for (int i = tid; i < 128 * FI / 4; i += 256) sh4[i] = hsrc[i];
    const float4* wsrc = (const float4*)W;
    #pragma unroll 2
    for (int i = tid; i < FI * FO / 4; i += 256) sW4[i] = wsrc[i];
    __syncthreads();

    const int fg   = tid & 7;    // feature group: f0 = fg*8
    const int rowg = tid >> 3;   // 0..31: rows rowg*4 .. +3

    float acc[4][8];
    #pragma unroll
    for (int r = 0; r < 4; ++r)
        #pragma unroll
        for (int c = 0; c < 8; ++c) acc[r][c] = 0.f;

    #pragma unroll 2
    for (int k4 = 0; k4 < FI / 4; ++k4) {
        float4 hv[4];
        #pragma unroll
        for (int r = 0; r < 4; ++r) hv[r] = sh4[(rowg * 4 + r) * (FI / 4) + k4];
        #pragma unroll
        for (int kk = 0; kk < 4; ++kk) {
            const float4 wa = sW4[(k4 * 4 + kk) * 16 + fg * 2];
            const float4 wb = sW4[(k4 * 4 + kk) * 16 + fg * 2 + 1];
            #pragma unroll
            for (int r = 0; r < 4; ++r) {
                const float hk = f4c(hv[r], kk);
                acc[r][0] = fmaf(hk, wa.x, acc[r][0]);
                acc[r][1] = fmaf(hk, wa.y, acc[r][1]);
                acc[r][2] = fmaf(hk, wa.z, acc[r][2]);
                acc[r][3] = fmaf(hk, wa.w, acc[r][3]);
                acc[r][4] = fmaf(hk, wb.x, acc[r][4]);
                acc[r][5] = fmaf(hk, wb.y, acc[r][5]);
                acc[r][6] = fmaf(hk, wb.z, acc[r][6]);
                acc[r][7] = fmaf(hk, wb.w, acc[r][7]);
            }
        }
    }

    // ---- s1/s2 partials over this thread's 8 features, reduce over fg lanes
    const float4* a4 = (const float4*)a;
    const float4 a1a = a4[fg * 2], a1b = a4[fg * 2 + 1];
    const float4 a2a = a4[16 + fg * 2], a2b = a4[16 + fg * 2 + 1];
    float s1p[4], s2p[4];
    #pragma unroll
    for (int r = 0; r < 4; ++r) {
        s1p[r] = acc[r][0] * a1a.x + acc[r][1] * a1a.y + acc[r][2] * a1a.z + acc[r][3] * a1a.w
               + acc[r][4] * a1b.x + acc[r][5] * a1b.y + acc[r][6] * a1b.z + acc[r][7] * a1b.w;
        s2p[r] = acc[r][0] * a2a.x + acc[r][1] * a2a.y + acc[r][2] * a2a.z + acc[r][3] * a2a.w
               + acc[r][4] * a2b.x + acc[r][5] * a2b.y + acc[r][6] * a2b.z + acc[r][7] * a2b.w;
    }
    #pragma unroll
    for (int off = 1; off < 8; off <<= 1)
        #pragma unroll
        for (int r = 0; r < 4; ++r) {
            s1p[r] += __shfl_xor_sync(0xffffffffu, s1p[r], off);
            s2p[r] += __shfl_xor_sync(0xffffffffu, s2p[r], off);
        }
    if (fg == 0) {
        float e2v[4], f2v[4];
        const int base = row0 + rowg * 4;
        #pragma unroll
        for (int r = 0; r < 4; ++r) {
            const float s1 = s1p[r], s2 = s2p[r];
            const float e1 = __expf(s1), f1 = __expf(0.2f * s1);
            g_srowP[base + r] = make_uint4(h2u(-s1, -s1), h2u(e1, e1), h2u(f1, f1), 0u);
            e2v[r] = __expf(s2);
            f2v[r] = __expf(0.2f * s2);
        }
        #pragma unroll
        for (int pr = 0; pr < 2; ++pr) {
            g_scolP[(base >> 1) + pr] = make_uint4(
                h2u(s2p[pr * 2], s2p[pr * 2 + 1]),
                h2u(e2v[pr * 2], e2v[pr * 2 + 1]),
                h2u(f2v[pr * 2], f2v[pr * 2 + 1]), 0u);
        }
    }

    // ---- fp16 plane, natural [row][f] layout
    #pragma unroll
    for (int r = 0; r < 4; ++r) {
        const int row = row0 + rowg * 4 + r;
        uint32_t hw[4];
        #pragma unroll
        for (int cp = 0; cp < 4; ++cp)
            hw[cp] = h2u(acc[r][cp * 2], acc[r][cp * 2 + 1]);
        *(uint4*)(g_Wh_h + (size_t)row * FO + fg * 8) = make_uint4(hw[0], hw[1], hw[2], hw[3]);
    }
}

// ---------------------------------------------------------------------------
// Kernel 2: fused GAT attention, fp16 mma.sync, K-split warps, 3-stage
// cp.async pipeline for Wh. adj arrives as prefetched bitmasks (registers).
// Denominator via ones-column (col 64) through the MMA.
// ---------------------------------------------------------------------------
#define SB_STRIDE 144            // 72 fp16 cols: 64 data + col64=1.0 + zeros
#define SB_PLANE  (64 * SB_STRIDE)          // 9216
#define NSTAGE 3
#define OFF_SB    16384                         // after 16KB scolp
#define GAT_SMEM  (OFF_SB + NSTAGE * SB_PLANE)  // 44032
#define ACC_STRIDE 76            // 9 blocks*8 + den + pad

__device__ __forceinline__ void stage_chunk(uint32_t swh, int buf, int rowbase, int tid) {
    const uint32_t wbase = swh + buf * SB_PLANE;
    #pragma unroll
    for (int q = 0; q < 2; ++q) {
        const int id  = tid + q * 256;     // 0..511
        const int row = id >> 3;
        const int c16 = id & 7;
        const __half* src = g_Wh_h + (size_t)(rowbase + row) * FO + c16 * 8;
        cpasync16(wbase + row * SB_STRIDE + c16 * 16, src);
    }
}

__global__ void __launch_bounds__(256, 2) gat_kernel(const int* __restrict__ adj,
                                                     float* __restrict__ out) {
    extern __shared__ __align__(16) unsigned char smem_raw[];
    uint4* scolp = (uint4*)smem_raw;                        // 16KB (per j-pair)
    float* accbuf = (float*)(smem_raw + OFF_SB);            // reuses staging
    const uint32_t swh = smem_u32(smem_raw) + OFF_SB;

    const int tid  = threadIdx.x;
    const int lane = tid & 31;
    const int wid  = tid >> 5;
    const int b    = blockIdx.y;
    const int i0   = blockIdx.x * TI;

    const int mb    = (wid & 3) * 16;   // warp row base (local, 0..48)
    const int khalf = wid >> 2;         // 0: k-slices 0-1, 1: k-slices 2-3
    const int lrl = mb + (lane >> 2);   // local row (lo)
    const int lrh = lrl + 8;
    const int qc  = (lane & 3) * 2;     // k-pair base within 16

    // preload packed scol pairs for batch b (16KB)
    {
        const uint4* src = g_scolP + b * (NN / 2);
        #pragma unroll 2
        for (int i = tid; i < NN / 2; i += 256) scolp[i] = src[i];
    }
    // one-time init: pad cols 64-71 -> (1.0h, 0...) in all stage buffers
    for (int id = tid; id < NSTAGE * 64; id += 256) {
        const int s = id >> 6, row = id & 63;
        *(uint4*)(smem_raw + OFF_SB + s * SB_PLANE + row * SB_STRIDE + 128) =
            make_uint4(0x3C00u, 0u, 0u, 0u);
    }

    const uint4 rplo = g_srowP[b * NN + i0 + lrl];
    const uint4 rphi = g_srowP[b * NN + i0 + lrh];
    const uint2* abl = g_adjbits + (size_t)(b * NN + i0 + lrl) * NCHUNK;
    const uint2* abh = g_adjbits + (size_t)(b * NN + i0 + lrh) * NCHUNK;

    stage_chunk(swh, 0, b * NN, tid);
    asm volatile("cp.async.commit_group;" ::: "memory");
    stage_chunk(swh, 1, b * NN + KT, tid);
    asm volatile("cp.async.commit_group;" ::: "memory");

    uint2 mcl = abl[0], mch = abh[0];     // masks for chunk 0
    __syncthreads();   // scolp + pad init visible

    float acc[9][4];   // blocks 0-7: cols 0-63; block 8: den (col 64)
    #pragma unroll
    for (int nt = 0; nt < 9; ++nt)
        #pragma unroll
        for (int k = 0; k < 4; ++k) acc[nt][k] = 0.f;

    const int lrow = (lane & 7) + (lane & 8);       // ldmatrix x4 row 0..15
    const int lcol = (lane >> 4) << 3;              // 0 or 8
    const int drow = lane & 15;                     // ldmatrix x2 row
    const int kq   = lane & 3;                      // pair sub-index

    #pragma unroll 1
    for (int t = 0; t < NCHUNK; ++t) {
        uint2 mnl, mnh;
        if (t + 1 < NCHUNK) { mnl = abl[t + 1]; mnh = abh[t + 1]; }
        if (t + 2 < NCHUNK) {
            stage_chunk(swh, (t + 2) % NSTAGE, b * NN + (t + 2) * KT, tid);
            asm volatile("cp.async.commit_group;" ::: "memory");
            asm volatile("cp.async.wait_group 2;" ::: "memory");
        } else if (t + 1 < NCHUNK) {
            asm volatile("cp.async.wait_group 1;" ::: "memory");
        } else {
            asm volatile("cp.async.wait_group 0;" ::: "memory");
        }
        __syncthreads();   // chunk t landed everywhere

        const uint32_t bufh = swh + (t % NSTAGE) * SB_PLANE;

        #pragma unroll
        for (int kt2 = 0; kt2 < 2; ++kt2) {
            const int ktg = khalf * 2 + kt2;          // this warp's k-slice
            const int kp  = ktg * 8 + kq;             // pair index 0..31
            const int jp  = t * 32 + kp;              // global j-pair index
            const uint4 c01 = scolp[jp];
            const uint4 c89 = scolp[jp + 4];

            // A fragments: p = bitsel(E,F, s2>-s1) pairwise, masked by adj bits
            uint32_t m;
            m = setgt2(c01.x, rplo.x);
            const uint32_t a0 = hmul2u(bsel(rplo.y, rplo.z, m), bsel(c01.y, c01.z, m))
                                & pairmask(mcl, kp);
            m = setgt2(c01.x, rphi.x);
            const uint32_t a1 = hmul2u(bsel(rphi.y, rphi.z, m), bsel(c01.y, c01.z, m))
                                & pairmask(mch, kp);
            m = setgt2(c89.x, rplo.x);
            const uint32_t a2 = hmul2u(bsel(rplo.y, rplo.z, m), bsel(c89.y, c89.z, m))
                                & pairmask(mcl, kp + 4);
            m = setgt2(c89.x, rphi.x);
            const uint32_t a3 = hmul2u(bsel(rphi.y, rphi.z, m), bsel(c89.y, c89.z, m))
                                & pairmask(mch, kp + 4);

            // B fragments: 64 data cols + ones column (den)
            const uint32_t rowoff = (uint32_t)(ktg * 16 + lrow) * SB_STRIDE + lcol * 2;
            #pragma unroll
            for (int ci = 0; ci < 4; ++ci) {
                uint32_t bt[4];
                ldsm4t(bt, bufh + rowoff + ci * 32);
                mma16816(acc[ci * 2 + 0], a0, a1, a2, a3, bt[0], bt[1]);
                mma16816(acc[ci * 2 + 1], a0, a1, a2, a3, bt[2], bt[3]);
            }
            uint32_t dt[2];
            ldsm2t(dt, bufh + (uint32_t)(ktg * 16 + drow) * SB_STRIDE + 128);
            mma16816(acc[8], a0, a1, a2, a3, dt[0], dt[1]);
        }
        mcl = mnl; mch = mnh;
        __syncthreads();   // all reads of buffer t done before re-staging
    }

    // ---- merge across khalf: khalf=1 publishes partials (staging is free)
    if (khalf) {
        #pragma unroll
        for (int nt = 0; nt < 8; ++nt) {
            *(float2*)(accbuf + lrl * ACC_STRIDE + nt * 8 + qc) =
                make_float2(acc[nt][0], acc[nt][1]);
            *(float2*)(accbuf + lrh * ACC_STRIDE + nt * 8 + qc) =
                make_float2(acc[nt][2], acc[nt][3]);
        }
        if ((lane & 3) == 0) {
            accbuf[lrl * ACC_STRIDE + 72] = acc[8][0];
            accbuf[lrh * ACC_STRIDE + 72] = acc[8][2];
        }
    }
    __syncthreads();

    if (!khalf) {
        float invl = 0.f, invh = 0.f;
        if ((lane & 3) == 0) {
            invl = 1.0f / (acc[8][0] + accbuf[lrl * ACC_STRIDE + 72]);
            invh = 1.0f / (acc[8][2] + accbuf[lrh * ACC_STRIDE + 72]);
        }
        invl = __shfl_sync(0xffffffffu, invl, lane & ~3);
        invh = __shfl_sync(0xffffffffu, invh, lane & ~3);
        float* outl = out + (size_t)(b * NN + i0 + lrl) * FO;
        float* outh = out + (size_t)(b * NN + i0 + lrh) * FO;
        #pragma unroll
        for (int nt = 0; nt < 8; ++nt) {
            const int cb = nt * 8 + qc;
            const float2 tl = *(const float2*)(accbuf + lrl * ACC_STRIDE + cb);
            const float2 th = *(const float2*)(accbuf + lrh * ACC_STRIDE + cb);
            float2 o;
            float v;
            v = (acc[nt][0] + tl.x) * invl; o.x = (v > 0.f) ? v : expm1f(v);
            v = (acc[nt][1] + tl.y) * invl; o.y = (v > 0.f) ? v : expm1f(v);
            *(float2*)(outl + cb) = o;
            v = (acc[nt][2] + th.x) * invh; o.x = (v > 0.f) ? v : expm1f(v);
            v = (acc[nt][3] + th.y) * invh; o.y = (v > 0.f) ? v : expm1f(v);
            *(float2*)(outh + cb) = o;
        }
    }
}

// ---------------------------------------------------------------------------
extern "C" void kernel_launch(void* const* d_in, const int* in_sizes, int n_in,
                              void* d_out, int out_size) {
    const float* h   = (const float*)d_in[0];   // [8,2048,128] f32
    const float* W   = (const float*)d_in[1];   // [128,64] f32
    const float* a   = (const float*)d_in[2];   // [128,1] f32
    const int*   adj = (const int*)d_in[3];     // [8,2048,2048] i32
    float* out = (float*)d_out;                 // [8,2048,64] f32

    cudaFuncSetAttribute(wh_mask_kernel, cudaFuncAttributeMaxDynamicSharedMemorySize, 98304);
    cudaFuncSetAttribute(gat_kernel, cudaFuncAttributeMaxDynamicSharedMemorySize, GAT_SMEM);

    wh_mask_kernel<<<WH_BLOCKS + MASK_BLOCKS, 256, 98304>>>(h, W, a, adj);
    dim3 grid(NN / TI, BB);
    gat_kernel<<<grid, 256, GAT_SMEM>>>(adj, out);
}

// round 14
// speedup vs baseline: 1.1667x; 1.1667x over previous
#include <cuda_runtime.h>
#include <cuda_bf16.h>
#include <cuda_fp16.h>
#include <cstdint>
#include <math.h>

#define BB 8
#define NN 2048
#define FI 128
#define FO 64
#define KT 64
#define TI 64
#define NCHUNK (NN / KT)

#define WH_BLOCKS (BB * NN / 128)     // 128
#define MASK_BLOCKS 896
#define MASK_WARPS (MASK_BLOCKS * 8)
#define RC (BB * NN * NCHUNK)         // 524288 row-chunks

// ---------------- scratch (static device arrays: allocation-free) ----------
__device__ __half g_Wh_h[(size_t)BB * NN * FO];     // [row][f] 2MB, fp16
__device__ uint4 g_srowP[BB * NN];       // (h2(-s1,-s1), h2(E1,E1), h2(F1,F1), 0)
__device__ uint4 g_scolP[BB * NN / 2];   // per j-pair: (h2(s2,s2'), h2(E2,E2'), h2(F2,F2'), 0)
__device__ uint4 g_adjbits[RC];          // per (row,chunk): w0..w3, wq bit l(0..15) = adj[4l+q]

// ---------------- helpers ---------------------------------------------------
__device__ __forceinline__ uint32_t smem_u32(const void* p) {
    uint32_t a;
    asm("{ .reg .u64 t; cvta.to.shared.u64 t, %1; cvt.u32.u64 %0, t; }" : "=r"(a) : "l"(p));
    return a;
}

__device__ __forceinline__ void mma16816(float* c, uint32_t a0, uint32_t a1,
                                         uint32_t a2, uint32_t a3,
                                         uint32_t b0, uint32_t b1) {
    asm volatile("mma.sync.aligned.m16n8k16.row.col.f32.f16.f16.f32 "
                 "{%0,%1,%2,%3}, {%4,%5,%6,%7}, {%8,%9}, {%0,%1,%2,%3};"
                 : "+f"(c[0]), "+f"(c[1]), "+f"(c[2]), "+f"(c[3])
                 : "r"(a0), "r"(a1), "r"(a2), "r"(a3), "r"(b0), "r"(b1));
}

__device__ __forceinline__ void ldsm4t(uint32_t* r, uint32_t addr) {
    asm volatile("ldmatrix.sync.aligned.m8n8.x4.trans.shared.b16 {%0,%1,%2,%3}, [%4];"
                 : "=r"(r[0]), "=r"(r[1]), "=r"(r[2]), "=r"(r[3]) : "r"(addr));
}

__device__ __forceinline__ void ldsm2t(uint32_t* r, uint32_t addr) {
    asm volatile("ldmatrix.sync.aligned.m8n8.x2.trans.shared.b16 {%0,%1}, [%2];"
                 : "=r"(r[0]), "=r"(r[1]) : "r"(addr));
}

__device__ __forceinline__ void cpasync16(uint32_t dst, const void* src) {
    asm volatile("cp.async.ca.shared.global [%0], [%1], 16;" :: "r"(dst), "l"(src));
}

__device__ __forceinline__ uint32_t h2u(float x, float y) {
    __half2 v = __float22half2_rn(make_float2(x, y));
    return *(uint32_t*)&v;
}

// per-half-lane 0xFFFF mask where a > b (fp16x2 compare)
__device__ __forceinline__ uint32_t setgt2(uint32_t a, uint32_t b) {
    uint32_t m;
    asm("set.gt.u32.f16x2 %0, %1, %2;" : "=r"(m) : "r"(a), "r"(b));
    return m;
}

__device__ __forceinline__ uint32_t hmul2u(uint32_t a, uint32_t b) {
    uint32_t d;
    asm("mul.f16x2 %0, %1, %2;" : "=r"(d) : "r"(a), "r"(b));
    return d;
}

// bit-select: (x & m) | (y & ~m)   -> single LOP3
__device__ __forceinline__ uint32_t bsel(uint32_t x, uint32_t y, uint32_t m) {
    return (x & m) | (y & ~m);
}

// (u, v) mask words -> packed halfword mask from bit q of each
__device__ __forceinline__ uint32_t pmk(uint32_t u, uint32_t v, int q) {
    return (((u >> q) & 1u) + (((v >> q) & 1u) << 16)) * 0xFFFFu;
}

__device__ __forceinline__ float f4c(const float4& v, int k) {
    return k == 0 ? v.x : (k == 1 ? v.y : (k == 2 ? v.z : v.w));
}

// ---------------------------------------------------------------------------
// Kernel A: blocks [0,128): Wh = h @ W + packed attention tables.
//           blocks [128, 128+896): adj -> bitmask compression (concurrent).
// One warp-step covers TWO row-chunks per int4/lane (128 contiguous ints):
// lanes 0-15 -> chunk 2c (bit l = adj[4l+q]), lanes 16-31 -> chunk 2c+1.
// ---------------------------------------------------------------------------
__global__ void __launch_bounds__(256, 2) wh_mask_kernel(const float* __restrict__ h,
                                                         const float* __restrict__ W,
                                                         const float* __restrict__ a,
                                                         const int* __restrict__ adj) {
    if (blockIdx.x >= WH_BLOCKS) {
        const int lane = threadIdx.x & 31;
        const int gw = (blockIdx.x - WH_BLOCKS) * 8 + (threadIdx.x >> 5);
        // each step: 2 row-chunks (128 ints); 8 steps unrolled -> 16 chunks
        for (int base = gw * 16; base < RC; base += MASK_WARPS * 16) {
            int4 v[8];
            #pragma unroll
            for (int u = 0; u < 8; ++u)
                v[u] = *(const int4*)(adj + (size_t)(base + 2 * u) * KT + lane * 4);
            #pragma unroll
            for (int u = 0; u < 8; ++u) {
                const uint32_t m0 = __ballot_sync(0xffffffffu, v[u].x);
                const uint32_t m1 = __ballot_sync(0xffffffffu, v[u].y);
                const uint32_t m2 = __ballot_sync(0xffffffffu, v[u].z);
                const uint32_t m3 = __ballot_sync(0xffffffffu, v[u].w);
                if (lane == 0)
                    g_adjbits[base + 2 * u] = make_uint4(m0 & 0xFFFFu, m1 & 0xFFFFu,
                                                         m2 & 0xFFFFu, m3 & 0xFFFFu);
                else if (lane == 1)
                    g_adjbits[base + 2 * u + 1] = make_uint4(m0 >> 16, m1 >> 16,
                                                             m2 >> 16, m3 >> 16);
            }
        }
        return;
    }

    // ---------------- Wh blocks (proven R10 body) ----------------
    extern __shared__ __align__(16) unsigned char smem_raw[];
    float4* sh4 = (float4*)smem_raw;                     // 128 x 128 f32 = 64KB
    float4* sW4 = (float4*)(smem_raw + 65536);           // 128 x 64 f32 = 32KB

    const int tid  = threadIdx.x;
    const int row0 = blockIdx.x * 128;

    const float4* hsrc = (const float4*)(h + (size_t)row0 * FI);
    #pragma unroll 4
    for (int i = tid; i < 128 * FI / 4; i += 256) sh4[i] = hsrc[i];
    const float4* wsrc = (const float4*)W;
    #pragma unroll 2
    for (int i = tid; i < FI * FO / 4; i += 256) sW4[i] = wsrc[i];
    __syncthreads();

    const int fg   = tid & 7;    // feature group: f0 = fg*8
    const int rowg = tid >> 3;   // 0..31: rows rowg*4 .. +3

    float acc[4][8];
    #pragma unroll
    for (int r = 0; r < 4; ++r)
        #pragma unroll
        for (int c = 0; c < 8; ++c) acc[r][c] = 0.f;

    #pragma unroll 2
    for (int k4 = 0; k4 < FI / 4; ++k4) {
        float4 hv[4];
        #pragma unroll
        for (int r = 0; r < 4; ++r) hv[r] = sh4[(rowg * 4 + r) * (FI / 4) + k4];
        #pragma unroll
        for (int kk = 0; kk < 4; ++kk) {
            const float4 wa = sW4[(k4 * 4 + kk) * 16 + fg * 2];
            const float4 wb = sW4[(k4 * 4 + kk) * 16 + fg * 2 + 1];
            #pragma unroll
            for (int r = 0; r < 4; ++r) {
                const float hk = f4c(hv[r], kk);
                acc[r][0] = fmaf(hk, wa.x, acc[r][0]);
                acc[r][1] = fmaf(hk, wa.y, acc[r][1]);
                acc[r][2] = fmaf(hk, wa.z, acc[r][2]);
                acc[r][3] = fmaf(hk, wa.w, acc[r][3]);
                acc[r][4] = fmaf(hk, wb.x, acc[r][4]);
                acc[r][5] = fmaf(hk, wb.y, acc[r][5]);
                acc[r][6] = fmaf(hk, wb.z, acc[r][6]);
                acc[r][7] = fmaf(hk, wb.w, acc[r][7]);
            }
        }
    }

    // ---- s1/s2 partials over this thread's 8 features, reduce over fg lanes
    const float4* a4 = (const float4*)a;
    const float4 a1a = a4[fg * 2], a1b = a4[fg * 2 + 1];
    const float4 a2a = a4[16 + fg * 2], a2b = a4[16 + fg * 2 + 1];
    float s1p[4], s2p[4];
    #pragma unroll
    for (int r = 0; r < 4; ++r) {
        s1p[r] = acc[r][0] * a1a.x + acc[r][1] * a1a.y + acc[r][2] * a1a.z + acc[r][3] * a1a.w
               + acc[r][4] * a1b.x + acc[r][5] * a1b.y + acc[r][6] * a1b.z + acc[r][7] * a1b.w;
        s2p[r] = acc[r][0] * a2a.x + acc[r][1] * a2a.y + acc[r][2] * a2a.z + acc[r][3] * a2a.w
               + acc[r][4] * a2b.x + acc[r][5] * a2b.y + acc[r][6] * a2b.z + acc[r][7] * a2b.w;
    }
    #pragma unroll
    for (int off = 1; off < 8; off <<= 1)
        #pragma unroll
        for (int r = 0; r < 4; ++r) {
            s1p[r] += __shfl_xor_sync(0xffffffffu, s1p[r], off);
            s2p[r] += __shfl_xor_sync(0xffffffffu, s2p[r], off);
        }
    if (fg == 0) {
        float e2v[4], f2v[4];
        const int base = row0 + rowg * 4;
        #pragma unroll
        for (int r = 0; r < 4; ++r) {
            const float s1 = s1p[r], s2 = s2p[r];
            const float e1 = __expf(s1), f1 = __expf(0.2f * s1);
            g_srowP[base + r] = make_uint4(h2u(-s1, -s1), h2u(e1, e1), h2u(f1, f1), 0u);
            e2v[r] = __expf(s2);
            f2v[r] = __expf(0.2f * s2);
        }
        #pragma unroll
        for (int pr = 0; pr < 2; ++pr) {
            g_scolP[(base >> 1) + pr] = make_uint4(
                h2u(s2p[pr * 2], s2p[pr * 2 + 1]),
                h2u(e2v[pr * 2], e2v[pr * 2 + 1]),
                h2u(f2v[pr * 2], f2v[pr * 2 + 1]), 0u);
        }
    }

    // ---- fp16 plane, natural [row][f] layout
    #pragma unroll
    for (int r = 0; r < 4; ++r) {
        const int row = row0 + rowg * 4 + r;
        uint32_t hw[4];
        #pragma unroll
        for (int cp = 0; cp < 4; ++cp)
            hw[cp] = h2u(acc[r][cp * 2], acc[r][cp * 2 + 1]);
        *(uint4*)(g_Wh_h + (size_t)row * FO + fg * 8) = make_uint4(hw[0], hw[1], hw[2], hw[3]);
    }
}

// ---------------------------------------------------------------------------
// Kernel 2: fused GAT attention, fp16 mma.sync, K-split warps, 4-stage
// cp.async pipeline for Wh (one barrier per chunk). adj via register-
// prefetched bitmasks. Denominator via ones-column (col 64) through MMA.
// ---------------------------------------------------------------------------
#define SB_STRIDE 144            // 72 fp16 cols: 64 data + col64=1.0 + zeros
#define SB_PLANE  (64 * SB_STRIDE)          // 9216
#define NSTAGE 4
#define OFF_SB    16384                         // after 16KB scolp
#define GAT_SMEM  (OFF_SB + NSTAGE * SB_PLANE)  // 53248
#define ACC_STRIDE 76            // 9 blocks*8 + den + pad

__device__ __forceinline__ void stage_chunk(uint32_t swh, int buf, int rowbase, int tid) {
    const uint32_t wbase = swh + buf * SB_PLANE;
    #pragma unroll
    for (int q = 0; q < 2; ++q) {
        const int id  = tid + q * 256;     // 0..511
        const int row = id >> 3;
        const int c16 = id & 7;
        const __half* src = g_Wh_h + (size_t)(rowbase + row) * FO + c16 * 8;
        cpasync16(wbase + row * SB_STRIDE + c16 * 16, src);
    }
}

__global__ void __launch_bounds__(256, 2) gat_kernel(const int* __restrict__ adj,
                                                     float* __restrict__ out) {
    extern __shared__ __align__(16) unsigned char smem_raw[];
    uint4* scolp = (uint4*)smem_raw;                        // 16KB (per j-pair)
    float* accbuf = (float*)(smem_raw + OFF_SB);            // reuses staging
    const uint32_t swh = smem_u32(smem_raw) + OFF_SB;

    const int tid  = threadIdx.x;
    const int lane = tid & 31;
    const int wid  = tid >> 5;
    const int b    = blockIdx.y;
    const int i0   = blockIdx.x * TI;

    const int mb    = (wid & 3) * 16;   // warp row base (local, 0..48)
    const int khalf = wid >> 2;         // 0: k-slices 0-1, 1: k-slices 2-3
    const int lrl = mb + (lane >> 2);   // local row (lo)
    const int lrh = lrl + 8;
    const int qc  = (lane & 3) * 2;     // k-pair base within 16

    // preload packed scol pairs for batch b (16KB)
    {
        const uint4* src = g_scolP + b * (NN / 2);
        #pragma unroll 2
        for (int i = tid; i < NN / 2; i += 256) scolp[i] = src[i];
    }
    // one-time init: pad cols 64-71 -> (1.0h, 0...) in all stage buffers
    for (int id = tid; id < NSTAGE * 64; id += 256) {
        const int s = id >> 6, row = id & 63;
        *(uint4*)(smem_raw + OFF_SB + s * SB_PLANE + row * SB_STRIDE + 128) =
            make_uint4(0x3C00u, 0u, 0u, 0u);
    }

    const uint4 rplo = g_srowP[b * NN + i0 + lrl];
    const uint4 rphi = g_srowP[b * NN + i0 + lrh];
    const uint4* abl = g_adjbits + (size_t)(b * NN + i0 + lrl) * NCHUNK;
    const uint4* abh = g_adjbits + (size_t)(b * NN + i0 + lrh) * NCHUNK;

    stage_chunk(swh, 0, b * NN, tid);
    asm volatile("cp.async.commit_group;" ::: "memory");
    stage_chunk(swh, 1, b * NN + KT, tid);
    asm volatile("cp.async.commit_group;" ::: "memory");

    uint4 mcl = abl[0], mch = abh[0];     // masks for chunk 0
    __syncthreads();   // scolp + pad init visible

    float acc[9][4];   // blocks 0-7: cols 0-63; block 8: den (col 64)
    #pragma unroll
    for (int nt = 0; nt < 9; ++nt)
        #pragma unroll
        for (int k = 0; k < 4; ++k) acc[nt][k] = 0.f;

    const int lrow = (lane & 7) + (lane & 8);       // ldmatrix x4 row 0..15
    const int lcol = (lane >> 4) << 3;              // 0 or 8
    const int drow = lane & 15;                     // ldmatrix x2 row
    const int kq   = lane & 3;                      // pair sub-index
    const int kodd = kq & 1;                        // which mask words
    const int bq   = kq >> 1;                       // sub-bit within slice

    #pragma unroll 1
    for (int t = 0; t < NCHUNK; ++t) {
        uint4 mnl, mnh;
        if (t + 1 < NCHUNK) { mnl = abl[t + 1]; mnh = abh[t + 1]; }
        if (t + 2 < NCHUNK) {
            stage_chunk(swh, (t + 2) % NSTAGE, b * NN + (t + 2) * KT, tid);
            asm volatile("cp.async.commit_group;" ::: "memory");
            asm volatile("cp.async.wait_group 2;" ::: "memory");
        } else if (t + 1 < NCHUNK) {
            asm volatile("cp.async.wait_group 1;" ::: "memory");
        } else {
            asm volatile("cp.async.wait_group 0;" ::: "memory");
        }
        __syncthreads();   // chunk t landed; single barrier per chunk (4 bufs)

        const uint32_t bufh = swh + (t % NSTAGE) * SB_PLANE;

        // mask words for this thread's pair parity (2 SELs per row)
        const uint32_t ual = kodd ? mcl.z : mcl.x;
        const uint32_t uvl = kodd ? mcl.w : mcl.y;
        const uint32_t uah = kodd ? mch.z : mch.x;
        const uint32_t uvh = kodd ? mch.w : mch.y;

        #pragma unroll
        for (int kt2 = 0; kt2 < 2; ++kt2) {
            const int ktg = khalf * 2 + kt2;          // this warp's k-slice
            const int kp  = ktg * 8 + kq;             // pair index 0..31
            const int jp  = t * 32 + kp;              // global j-pair index
            const int bit = ktg * 4 + bq;             // mask bit for c01
            const uint4 c01 = scolp[jp];
            const uint4 c89 = scolp[jp + 4];

            // A fragments: p = bitsel(E,F, s2>-s1) pairwise, masked by adj bits
            uint32_t m;
            m = setgt2(c01.x, rplo.x);
            const uint32_t a0 = hmul2u(bsel(rplo.y, rplo.z, m), bsel(c01.y, c01.z, m))
                                & pmk(ual, uvl, bit);
            m = setgt2(c01.x, rphi.x);
            const uint32_t a1 = hmul2u(bsel(rphi.y, rphi.z, m), bsel(c01.y, c01.z, m))
                                & pmk(uah, uvh, bit);
            m = setgt2(c89.x, rplo.x);
            const uint32_t a2 = hmul2u(bsel(rplo.y, rplo.z, m), bsel(c89.y, c89.z, m))
                                & pmk(ual, uvl, bit + 2);
            m = setgt2(c89.x, rphi.x);
            const uint32_t a3 = hmul2u(bsel(rphi.y, rphi.z, m), bsel(c89.y, c89.z, m))
                                & pmk(uah, uvh, bit + 2);

            // B fragments: 64 data cols + ones column (den)
            const uint32_t rowoff = (uint32_t)(ktg * 16 + lrow) * SB_STRIDE + lcol * 2;
            #pragma unroll
            for (int ci = 0; ci < 4; ++ci) {
                uint32_t bt[4];
                ldsm4t(bt, bufh + rowoff + ci * 32);
                mma16816(acc[ci * 2 + 0], a0, a1, a2, a3, bt[0], bt[1]);
                mma16816(acc[ci * 2 + 1], a0, a1, a2, a3, bt[2], bt[3]);
            }
            uint32_t dt[2];
            ldsm2t(dt, bufh + (uint32_t)(ktg * 16 + drow) * SB_STRIDE + 128);
            mma16816(acc[8], a0, a1, a2, a3, dt[0], dt[1]);
        }
        mcl = mnl; mch = mnh;
        // no trailing barrier: top-of-loop barrier bounds skew; buf (t+2)%4
        // can never be a buffer a laggard is still reading
    }

    __syncthreads();   // staging region now reusable for the acc exchange

    // ---- merge across khalf: khalf=1 publishes partials
    if (khalf) {
        #pragma unroll
        for (int nt = 0; nt < 8; ++nt) {
            *(float2*)(accbuf + lrl * ACC_STRIDE + nt * 8 + qc) =
                make_float2(acc[nt][0], acc[nt][1]);
            *(float2*)(accbuf + lrh * ACC_STRIDE + nt * 8 + qc) =
                make_float2(acc[nt][2], acc[nt][3]);
        }
        if ((lane & 3) == 0) {
            accbuf[lrl * ACC_STRIDE + 72] = acc[8][0];
            accbuf[lrh * ACC_STRIDE + 72] = acc[8][2];
        }
    }
    __syncthreads();

    if (!khalf) {
        float invl = 0.f, invh = 0.f;
        if ((lane & 3) == 0) {
            invl = 1.0f / (acc[8][0] + accbuf[lrl * ACC_STRIDE + 72]);
            invh = 1.0f / (acc[8][2] + accbuf[lrh * ACC_STRIDE + 72]);
        }
        invl = __shfl_sync(0xffffffffu, invl, lane & ~3);
        invh = __shfl_sync(0xffffffffu, invh, lane & ~3);
        float* outl = out + (size_t)(b * NN + i0 + lrl) * FO;
        float* outh = out + (size_t)(b * NN + i0 + lrh) * FO;
        #pragma unroll
        for (int nt = 0; nt < 8; ++nt) {
            const int cb = nt * 8 + qc;
            const float2 tl = *(const float2*)(accbuf + lrl * ACC_STRIDE + cb);
            const float2 th = *(const float2*)(accbuf + lrh * ACC_STRIDE + cb);
            float2 o;
            float v;
            v = (acc[nt][0] + tl.x) * invl; o.x = (v > 0.f) ? v : expm1f(v);
            v = (acc[nt][1] + tl.y) * invl; o.y = (v > 0.f) ? v : expm1f(v);
            *(float2*)(outl + cb) = o;
            v = (acc[nt][2] + th.x) * invh; o.x = (v > 0.f) ? v : expm1f(v);
            v = (acc[nt][3] + th.y) * invh; o.y = (v > 0.f) ? v : expm1f(v);
            *(float2*)(outh + cb) = o;
        }
    }
}

// ---------------------------------------------------------------------------
extern "C" void kernel_launch(void* const* d_in, const int* in_sizes, int n_in,
                              void* d_out, int out_size) {
    const float* h   = (const float*)d_in[0];   // [8,2048,128] f32
    const float* W   = (const float*)d_in[1];   // [128,64] f32
    const float* a   = (const float*)d_in[2];   // [128,1] f32
    const int*   adj = (const int*)d_in[3];     // [8,2048,2048] i32
    float* out = (float*)d_out;                 // [8,2048,64] f32

    cudaFuncSetAttribute(wh_mask_kernel, cudaFuncAttributeMaxDynamicSharedMemorySize, 98304);
    cudaFuncSetAttribute(gat_kernel, cudaFuncAttributeMaxDynamicSharedMemorySize, GAT_SMEM);

    wh_mask_kernel<<<WH_BLOCKS + MASK_BLOCKS, 256, 98304>>>(h, W, a, adj);
    dim3 grid(NN / TI, BB);
    gat_kernel<<<grid, 256, GAT_SMEM>>>(adj, out);
}

// round 15
// speedup vs baseline: 1.2727x; 1.0909x over previous
#include <cuda_runtime.h>
#include <cuda_bf16.h>
#include <cuda_fp16.h>
#include <cstdint>
#include <math.h>

#define BB 8
#define NN 2048
#define FI 128
#define FO 64
#define KT 64
#define TI 64
#define NCHUNK (NN / KT)

#define WH_BLOCKS (BB * NN / 128)     // 128
#define MASK_BLOCKS 896
#define MASK_WARPS (MASK_BLOCKS * 8)
#define RC (BB * NN * NCHUNK)         // 524288 row-chunks

// ---------------- scratch (static device arrays: allocation-free) ----------
__device__ __half g_Wh_h[(size_t)BB * NN * FO];     // [row][f] 2MB, fp16
__device__ uint4 g_srowP[BB * NN];       // (h2(-s1,-s1), h2(E1,E1), h2(F1,F1), 0)
__device__ uint4 g_scolP[BB * NN / 2];   // per j-pair: (h2(s2,s2'), h2(E2,E2'), h2(F2,F2'), 0)
__device__ uint4 g_adjbits[RC];          // per (row,chunk): w0..w3, wq bit l(0..15) = adj[4l+q]

// ---------------- helpers ---------------------------------------------------
__device__ __forceinline__ uint32_t smem_u32(const void* p) {
    uint32_t a;
    asm("{ .reg .u64 t; cvta.to.shared.u64 t, %1; cvt.u32.u64 %0, t; }" : "=r"(a) : "l"(p));
    return a;
}

__device__ __forceinline__ void mma16816(float* c, uint32_t a0, uint32_t a1,
                                         uint32_t a2, uint32_t a3,
                                         uint32_t b0, uint32_t b1) {
    asm volatile("mma.sync.aligned.m16n8k16.row.col.f32.f16.f16.f32 "
                 "{%0,%1,%2,%3}, {%4,%5,%6,%7}, {%8,%9}, {%0,%1,%2,%3};"
                 : "+f"(c[0]), "+f"(c[1]), "+f"(c[2]), "+f"(c[3])
                 : "r"(a0), "r"(a1), "r"(a2), "r"(a3), "r"(b0), "r"(b1));
}

__device__ __forceinline__ void ldsm4t(uint32_t* r, uint32_t addr) {
    asm volatile("ldmatrix.sync.aligned.m8n8.x4.trans.shared.b16 {%0,%1,%2,%3}, [%4];"
                 : "=r"(r[0]), "=r"(r[1]), "=r"(r[2]), "=r"(r[3]) : "r"(addr));
}

__device__ __forceinline__ void ldsm2t(uint32_t* r, uint32_t addr) {
    asm volatile("ldmatrix.sync.aligned.m8n8.x2.trans.shared.b16 {%0,%1}, [%2];"
                 : "=r"(r[0]), "=r"(r[1]) : "r"(addr));
}

__device__ __forceinline__ void cpasync16(uint32_t dst, const void* src) {
    asm volatile("cp.async.ca.shared.global [%0], [%1], 16;" :: "r"(dst), "l"(src));
}

__device__ __forceinline__ uint32_t h2u(float x, float y) {
    __half2 v = __float22half2_rn(make_float2(x, y));
    return *(uint32_t*)&v;
}

// per-half-lane 0xFFFF mask where a > b (fp16x2 compare)
__device__ __forceinline__ uint32_t setgt2(uint32_t a, uint32_t b) {
    uint32_t m;
    asm("set.gt.u32.f16x2 %0, %1, %2;" : "=r"(m) : "r"(a), "r"(b));
    return m;
}

__device__ __forceinline__ uint32_t hmul2u(uint32_t a, uint32_t b) {
    uint32_t d;
    asm("mul.f16x2 %0, %1, %2;" : "=r"(d) : "r"(a), "r"(b));
    return d;
}

// bit-select: (x & m) | (y & ~m)   -> single LOP3
__device__ __forceinline__ uint32_t bsel(uint32_t x, uint32_t y, uint32_t m) {
    return (x & m) | (y & ~m);
}

// (u, v) mask words -> packed halfword mask from bit q of each
__device__ __forceinline__ uint32_t pmk(uint32_t u, uint32_t v, int q) {
    return (((u >> q) & 1u) + (((v >> q) & 1u) << 16)) * 0xFFFFu;
}

__device__ __forceinline__ float f4c(const float4& v, int k) {
    return k == 0 ? v.x : (k == 1 ? v.y : (k == 2 ? v.z : v.w));
}

// ---------------------------------------------------------------------------
// Kernel A (NO dynamic smem; 32KB static for W only -> 3 CTAs/SM):
//   blocks [0,128): Wh = h @ W + packed attention tables (h read via __ldg).
//   blocks [128, 128+896): adj -> bitmask compression (concurrent, smem-free).
// ---------------------------------------------------------------------------
__global__ void __launch_bounds__(256, 3) wh_mask_kernel(const float* __restrict__ h,
                                                         const float* __restrict__ W,
                                                         const float* __restrict__ a,
                                                         const int* __restrict__ adj) {
    __shared__ float4 sW4[FI * FO / 4];   // 32 KB static

    if (blockIdx.x >= WH_BLOCKS) {
        // ------- mask compression (R13-validated): 2 row-chunks per int4 ----
        const int lane = threadIdx.x & 31;
        const int gw = (blockIdx.x - WH_BLOCKS) * 8 + (threadIdx.x >> 5);
        for (int base = gw * 16; base < RC; base += MASK_WARPS * 16) {
            int4 v[8];
            #pragma unroll
            for (int u = 0; u < 8; ++u)
                v[u] = *(const int4*)(adj + (size_t)(base + 2 * u) * KT + lane * 4);
            #pragma unroll
            for (int u = 0; u < 8; ++u) {
                const uint32_t m0 = __ballot_sync(0xffffffffu, v[u].x);
                const uint32_t m1 = __ballot_sync(0xffffffffu, v[u].y);
                const uint32_t m2 = __ballot_sync(0xffffffffu, v[u].z);
                const uint32_t m3 = __ballot_sync(0xffffffffu, v[u].w);
                if (lane == 0)
                    g_adjbits[base + 2 * u] = make_uint4(m0 & 0xFFFFu, m1 & 0xFFFFu,
                                                         m2 & 0xFFFFu, m3 & 0xFFFFu);
                else if (lane == 1)
                    g_adjbits[base + 2 * u + 1] = make_uint4(m0 >> 16, m1 >> 16,
                                                             m2 >> 16, m3 >> 16);
            }
        }
        return;
    }

    // ---------------- Wh blocks: W in smem, h via __ldg (L1-resident) -------
    const int tid  = threadIdx.x;
    const int row0 = blockIdx.x * 128;

    const float4* wsrc = (const float4*)W;
    #pragma unroll 2
    for (int i = tid; i < FI * FO / 4; i += 256) sW4[i] = wsrc[i];
    __syncthreads();

    const int fg   = tid & 7;    // feature group: f0 = fg*8
    const int rowg = tid >> 3;   // 0..31: rows rowg*4 .. +3
    const float4* hrow = (const float4*)(h + (size_t)(row0 + rowg * 4) * FI);

    float acc[4][8];
    #pragma unroll
    for (int r = 0; r < 4; ++r)
        #pragma unroll
        for (int c = 0; c < 8; ++c) acc[r][c] = 0.f;

    #pragma unroll 2
    for (int k4 = 0; k4 < FI / 4; ++k4) {
        float4 hv[4];
        #pragma unroll
        for (int r = 0; r < 4; ++r) hv[r] = __ldg(hrow + r * (FI / 4) + k4);
        #pragma unroll
        for (int kk = 0; kk < 4; ++kk) {
            const float4 wa = sW4[(k4 * 4 + kk) * 16 + fg * 2];
            const float4 wb = sW4[(k4 * 4 + kk) * 16 + fg * 2 + 1];
            #pragma unroll
            for (int r = 0; r < 4; ++r) {
                const float hk = f4c(hv[r], kk);
                acc[r][0] = fmaf(hk, wa.x, acc[r][0]);
                acc[r][1] = fmaf(hk, wa.y, acc[r][1]);
                acc[r][2] = fmaf(hk, wa.z, acc[r][2]);
                acc[r][3] = fmaf(hk, wa.w, acc[r][3]);
                acc[r][4] = fmaf(hk, wb.x, acc[r][4]);
                acc[r][5] = fmaf(hk, wb.y, acc[r][5]);
                acc[r][6] = fmaf(hk, wb.z, acc[r][6]);
                acc[r][7] = fmaf(hk, wb.w, acc[r][7]);
            }
        }
    }

    // ---- s1/s2 partials over this thread's 8 features, reduce over fg lanes
    const float4* a4 = (const float4*)a;
    const float4 a1a = a4[fg * 2], a1b = a4[fg * 2 + 1];
    const float4 a2a = a4[16 + fg * 2], a2b = a4[16 + fg * 2 + 1];
    float s1p[4], s2p[4];
    #pragma unroll
    for (int r = 0; r < 4; ++r) {
        s1p[r] = acc[r][0] * a1a.x + acc[r][1] * a1a.y + acc[r][2] * a1a.z + acc[r][3] * a1a.w
               + acc[r][4] * a1b.x + acc[r][5] * a1b.y + acc[r][6] * a1b.z + acc[r][7] * a1b.w;
        s2p[r] = acc[r][0] * a2a.x + acc[r][1] * a2a.y + acc[r][2] * a2a.z + acc[r][3] * a2a.w
               + acc[r][4] * a2b.x + acc[r][5] * a2b.y + acc[r][6] * a2b.z + acc[r][7] * a2b.w;
    }
    #pragma unroll
    for (int off = 1; off < 8; off <<= 1)
        #pragma unroll
        for (int r = 0; r < 4; ++r) {
            s1p[r] += __shfl_xor_sync(0xffffffffu, s1p[r], off);
            s2p[r] += __shfl_xor_sync(0xffffffffu, s2p[r], off);
        }
    if (fg == 0) {
        float e2v[4], f2v[4];
        const int base = row0 + rowg * 4;
        #pragma unroll
        for (int r = 0; r < 4; ++r) {
            const float s1 = s1p[r], s2 = s2p[r];
            const float e1 = __expf(s1), f1 = __expf(0.2f * s1);
            g_srowP[base + r] = make_uint4(h2u(-s1, -s1), h2u(e1, e1), h2u(f1, f1), 0u);
            e2v[r] = __expf(s2);
            f2v[r] = __expf(0.2f * s2);
        }
        #pragma unroll
        for (int pr = 0; pr < 2; ++pr) {
            g_scolP[(base >> 1) + pr] = make_uint4(
                h2u(s2p[pr * 2], s2p[pr * 2 + 1]),
                h2u(e2v[pr * 2], e2v[pr * 2 + 1]),
                h2u(f2v[pr * 2], f2v[pr * 2 + 1]), 0u);
        }
    }

    // ---- fp16 plane, natural [row][f] layout
    #pragma unroll
    for (int r = 0; r < 4; ++r) {
        const int row = row0 + rowg * 4 + r;
        uint32_t hw[4];
        #pragma unroll
        for (int cp = 0; cp < 4; ++cp)
            hw[cp] = h2u(acc[r][cp * 2], acc[r][cp * 2 + 1]);
        *(uint4*)(g_Wh_h + (size_t)row * FO + fg * 8) = make_uint4(hw[0], hw[1], hw[2], hw[3]);
    }
}

// ---------------------------------------------------------------------------
// Kernel 2: fused GAT attention (unchanged from R13, validated at 36.1us):
// fp16 mma.sync, K-split warps, 4-stage cp.async Wh pipeline, one barrier
// per chunk, adj via register-prefetched bitmasks, den via ones-column MMA.
// ---------------------------------------------------------------------------
#define SB_STRIDE 144            // 72 fp16 cols: 64 data + col64=1.0 + zeros
#define SB_PLANE  (64 * SB_STRIDE)          // 9216
#define NSTAGE 4
#define OFF_SB    16384                         // after 16KB scolp
#define GAT_SMEM  (OFF_SB + NSTAGE * SB_PLANE)  // 53248
#define ACC_STRIDE 76            // 9 blocks*8 + den + pad

__device__ __forceinline__ void stage_chunk(uint32_t swh, int buf, int rowbase, int tid) {
    const uint32_t wbase = swh + buf * SB_PLANE;
    #pragma unroll
    for (int q = 0; q < 2; ++q) {
        const int id  = tid + q * 256;     // 0..511
        const int row = id >> 3;
        const int c16 = id & 7;
        const __half* src = g_Wh_h + (size_t)(rowbase + row) * FO + c16 * 8;
        cpasync16(wbase + row * SB_STRIDE + c16 * 16, src);
    }
}

__global__ void __launch_bounds__(256, 2) gat_kernel(const int* __restrict__ adj,
                                                     float* __restrict__ out) {
    extern __shared__ __align__(16) unsigned char smem_raw[];
    uint4* scolp = (uint4*)smem_raw;                        // 16KB (per j-pair)
    float* accbuf = (float*)(smem_raw + OFF_SB);            // reuses staging
    const uint32_t swh = smem_u32(smem_raw) + OFF_SB;

    const int tid  = threadIdx.x;
    const int lane = tid & 31;
    const int wid  = tid >> 5;
    const int b    = blockIdx.y;
    const int i0   = blockIdx.x * TI;

    const int mb    = (wid & 3) * 16;   // warp row base (local, 0..48)
    const int khalf = wid >> 2;         // 0: k-slices 0-1, 1: k-slices 2-3
    const int lrl = mb + (lane >> 2);   // local row (lo)
    const int lrh = lrl + 8;
    const int qc  = (lane & 3) * 2;     // k-pair base within 16

    // preload packed scol pairs for batch b (16KB)
    {
        const uint4* src = g_scolP + b * (NN / 2);
        #pragma unroll 2
        for (int i = tid; i < NN / 2; i += 256) scolp[i] = src[i];
    }
    // one-time init: pad cols 64-71 -> (1.0h, 0...) in all stage buffers
    for (int id = tid; id < NSTAGE * 64; id += 256) {
        const int s = id >> 6, row = id & 63;
        *(uint4*)(smem_raw + OFF_SB + s * SB_PLANE + row * SB_STRIDE + 128) =
            make_uint4(0x3C00u, 0u, 0u, 0u);
    }

    const uint4 rplo = g_srowP[b * NN + i0 + lrl];
    const uint4 rphi = g_srowP[b * NN + i0 + lrh];
    const uint4* abl = g_adjbits + (size_t)(b * NN + i0 + lrl) * NCHUNK;
    const uint4* abh = g_adjbits + (size_t)(b * NN + i0 + lrh) * NCHUNK;

    stage_chunk(swh, 0, b * NN, tid);
    asm volatile("cp.async.commit_group;" ::: "memory");
    stage_chunk(swh, 1, b * NN + KT, tid);
    asm volatile("cp.async.commit_group;" ::: "memory");

    uint4 mcl = abl[0], mch = abh[0];     // masks for chunk 0
    __syncthreads();   // scolp + pad init visible

    float acc[9][4];   // blocks 0-7: cols 0-63; block 8: den (col 64)
    #pragma unroll
    for (int nt = 0; nt < 9; ++nt)
        #pragma unroll
        for (int k = 0; k < 4; ++k) acc[nt][k] = 0.f;

    const int lrow = (lane & 7) + (lane & 8);       // ldmatrix x4 row 0..15
    const int lcol = (lane >> 4) << 3;              // 0 or 8
    const int drow = lane & 15;                     // ldmatrix x2 row
    const int kq   = lane & 3;                      // pair sub-index
    const int kodd = kq & 1;                        // which mask words
    const int bq   = kq >> 1;                       // sub-bit within slice

    #pragma unroll 1
    for (int t = 0; t < NCHUNK; ++t) {
        uint4 mnl, mnh;
        if (t + 1 < NCHUNK) { mnl = abl[t + 1]; mnh = abh[t + 1]; }
        if (t + 2 < NCHUNK) {
            stage_chunk(swh, (t + 2) % NSTAGE, b * NN + (t + 2) * KT, tid);
            asm volatile("cp.async.commit_group;" ::: "memory");
            asm volatile("cp.async.wait_group 2;" ::: "memory");
        } else if (t + 1 < NCHUNK) {
            asm volatile("cp.async.wait_group 1;" ::: "memory");
        } else {
            asm volatile("cp.async.wait_group 0;" ::: "memory");
        }
        __syncthreads();   // chunk t landed; single barrier per chunk (4 bufs)

        const uint32_t bufh = swh + (t % NSTAGE) * SB_PLANE;

        // mask words for this thread's pair parity (2 SELs per row)
        const uint32_t ual = kodd ? mcl.z : mcl.x;
        const uint32_t uvl = kodd ? mcl.w : mcl.y;
        const uint32_t uah = kodd ? mch.z : mch.x;
        const uint32_t uvh = kodd ? mch.w : mch.y;

        #pragma unroll
        for (int kt2 = 0; kt2 < 2; ++kt2) {
            const int ktg = khalf * 2 + kt2;          // this warp's k-slice
            const int kp  = ktg * 8 + kq;             // pair index 0..31
            const int jp  = t * 32 + kp;              // global j-pair index
            const int bit = ktg * 4 + bq;             // mask bit for c01
            const uint4 c01 = scolp[jp];
            const uint4 c89 = scolp[jp + 4];

            // A fragments: p = bitsel(E,F, s2>-s1) pairwise, masked by adj bits
            uint32_t m;
            m = setgt2(c01.x, rplo.x);
            const uint32_t a0 = hmul2u(bsel(rplo.y, rplo.z, m), bsel(c01.y, c01.z, m))
                                & pmk(ual, uvl, bit);
            m = setgt2(c01.x, rphi.x);
            const uint32_t a1 = hmul2u(bsel(rphi.y, rphi.z, m), bsel(c01.y, c01.z, m))
                                & pmk(uah, uvh, bit);
            m = setgt2(c89.x, rplo.x);
            const uint32_t a2 = hmul2u(bsel(rplo.y, rplo.z, m), bsel(c89.y, c89.z, m))
                                & pmk(ual, uvl, bit + 2);
            m = setgt2(c89.x, rphi.x);
            const uint32_t a3 = hmul2u(bsel(rphi.y, rphi.z, m), bsel(c89.y, c89.z, m))
                                & pmk(uah, uvh, bit + 2);

            // B fragments: 64 data cols + ones column (den)
            const uint32_t rowoff = (uint32_t)(ktg * 16 + lrow) * SB_STRIDE + lcol * 2;
            #pragma unroll
            for (int ci = 0; ci < 4; ++ci) {
                uint32_t bt[4];
                ldsm4t(bt, bufh + rowoff + ci * 32);
                mma16816(acc[ci * 2 + 0], a0, a1, a2, a3, bt[0], bt[1]);
                mma16816(acc[ci * 2 + 1], a0, a1, a2, a3, bt[2], bt[3]);
            }
            uint32_t dt[2];
            ldsm2t(dt, bufh + (uint32_t)(ktg * 16 + drow) * SB_STRIDE + 128);
            mma16816(acc[8], a0, a1, a2, a3, dt[0], dt[1]);
        }
        mcl = mnl; mch = mnh;
        // no trailing barrier: top-of-loop barrier bounds skew; buf (t+2)%4
        // can never be a buffer a laggard is still reading
    }

    __syncthreads();   // staging region now reusable for the acc exchange

    // ---- merge across khalf: khalf=1 publishes partials
    if (khalf) {
        #pragma unroll
        for (int nt = 0; nt < 8; ++nt) {
            *(float2*)(accbuf + lrl * ACC_STRIDE + nt * 8 + qc) =
                make_float2(acc[nt][0], acc[nt][1]);
            *(float2*)(accbuf + lrh * ACC_STRIDE + nt * 8 + qc) =
                make_float2(acc[nt][2], acc[nt][3]);
        }
        if ((lane & 3) == 0) {
            accbuf[lrl * ACC_STRIDE + 72] = acc[8][0];
            accbuf[lrh * ACC_STRIDE + 72] = acc[8][2];
        }
    }
    __syncthreads();

    if (!khalf) {
        float invl = 0.f, invh = 0.f;
        if ((lane & 3) == 0) {
            invl = 1.0f / (acc[8][0] + accbuf[lrl * ACC_STRIDE + 72]);
            invh = 1.0f / (acc[8][2] + accbuf[lrh * ACC_STRIDE + 72]);
        }
        invl = __shfl_sync(0xffffffffu, invl, lane & ~3);
        invh = __shfl_sync(0xffffffffu, invh, lane & ~3);
        float* outl = out + (size_t)(b * NN + i0 + lrl) * FO;
        float* outh = out + (size_t)(b * NN + i0 + lrh) * FO;
        #pragma unroll
        for (int nt = 0; nt < 8; ++nt) {
            const int cb = nt * 8 + qc;
            const float2 tl = *(const float2*)(accbuf + lrl * ACC_STRIDE + cb);
            const float2 th = *(const float2*)(accbuf + lrh * ACC_STRIDE + cb);
            float2 o;
            float v;
            v = (acc[nt][0] + tl.x) * invl; o.x = (v > 0.f) ? v : expm1f(v);
            v = (acc[nt][1] + tl.y) * invl; o.y = (v > 0.f) ? v : expm1f(v);
            *(float2*)(outl + cb) = o;
            v = (acc[nt][2] + th.x) * invh; o.x = (v > 0.f) ? v : expm1f(v);
            v = (acc[nt][3] + th.y) * invh; o.y = (v > 0.f) ? v : expm1f(v);
            *(float2*)(outh + cb) = o;
        }
    }
}

// ---------------------------------------------------------------------------
extern "C" void kernel_launch(void* const* d_in, const int* in_sizes, int n_in,
                              void* d_out, int out_size) {
    const float* h   = (const float*)d_in[0];   // [8,2048,128] f32
    const float* W   = (const float*)d_in[1];   // [128,64] f32
    const float* a   = (const float*)d_in[2];   // [128,1] f32
    const int*   adj = (const int*)d_in[3];     // [8,2048,2048] i32
    float* out = (float*)d_out;                 // [8,2048,64] f32

    cudaFuncSetAttribute(gat_kernel, cudaFuncAttributeMaxDynamicSharedMemorySize, GAT_SMEM);

    wh_mask_kernel<<<WH_BLOCKS + MASK_BLOCKS, 256>>>(h, W, a, adj);
    dim3 grid(NN / TI, BB);
    gat_kernel<<<grid, 256, GAT_SMEM>>>(adj, out);
}

// round 17
// speedup vs baseline: 1.3125x; 1.0313x over previous
#include <cuda_runtime.h>
#include <cuda_bf16.h>
#include <cuda_fp16.h>
#include <cstdint>
#include <math.h>

#define BB 8
#define NN 2048
#define FI 128
#define FO 64
#define KT 128
#define TI 64
#define NCHUNK (NN / KT)              // 16

#define WH_BLOCKS (BB * NN / 128)     // 128
#define MASK_BLOCKS 896
#define MASK_WARPS (MASK_BLOCKS * 8)
#define RC (BB * NN * (NN / 64))      // 524288 row-granules (64-j each)

// ---------------- scratch (static device arrays: allocation-free) ----------
__device__ __half g_Wh_h[(size_t)BB * NN * FO];     // [row][f] 2MB, fp16
__device__ uint4 g_srowP[BB * NN];       // (h2(-s1,-s1), h2(E1,E1), h2(F1,F1), 0)
__device__ uint4 g_scolP[BB * NN / 2];   // per j-pair: (h2(s2,s2'), h2(E2,E2'), h2(F2,F2'), 0)
__device__ uint4 g_adjbits[RC];          // per (row, 64j-granule): w0..w3, wq bit l(0..15) = adj[4l+q]

// ---------------- helpers ---------------------------------------------------
__device__ __forceinline__ uint32_t smem_u32(const void* p) {
    uint32_t a;
    asm("{ .reg .u64 t; cvta.to.shared.u64 t, %1; cvt.u32.u64 %0, t; }" : "=r"(a) : "l"(p));
    return a;
}

__device__ __forceinline__ void mma16816(float* c, uint32_t a0, uint32_t a1,
                                         uint32_t a2, uint32_t a3,
                                         uint32_t b0, uint32_t b1) {
    asm volatile("mma.sync.aligned.m16n8k16.row.col.f32.f16.f16.f32 "
                 "{%0,%1,%2,%3}, {%4,%5,%6,%7}, {%8,%9}, {%0,%1,%2,%3};"
                 : "+f"(c[0]), "+f"(c[1]), "+f"(c[2]), "+f"(c[3])
                 : "r"(a0), "r"(a1), "r"(a2), "r"(a3), "r"(b0), "r"(b1));
}

__device__ __forceinline__ void ldsm4t(uint32_t* r, uint32_t addr) {
    asm volatile("ldmatrix.sync.aligned.m8n8.x4.trans.shared.b16 {%0,%1,%2,%3}, [%4];"
                 : "=r"(r[0]), "=r"(r[1]), "=r"(r[2]), "=r"(r[3]) : "r"(addr));
}

__device__ __forceinline__ void ldsm2t(uint32_t* r, uint32_t addr) {
    asm volatile("ldmatrix.sync.aligned.m8n8.x2.trans.shared.b16 {%0,%1}, [%2];"
                 : "=r"(r[0]), "=r"(r[1]) : "r"(addr));
}

__device__ __forceinline__ void cpasync16(uint32_t dst, const void* src) {
    asm volatile("cp.async.ca.shared.global [%0], [%1], 16;" :: "r"(dst), "l"(src));
}

__device__ __forceinline__ uint32_t h2u(float x, float y) {
    __half2 v = __float22half2_rn(make_float2(x, y));
    return *(uint32_t*)&v;
}

// per-half-lane 0xFFFF mask where a > b (fp16x2 compare)
__device__ __forceinline__ uint32_t setgt2(uint32_t a, uint32_t b) {
    uint32_t m;
    asm("set.gt.u32.f16x2 %0, %1, %2;" : "=r"(m) : "r"(a), "r"(b));
    return m;
}

__device__ __forceinline__ uint32_t hmul2u(uint32_t a, uint32_t b) {
    uint32_t d;
    asm("mul.f16x2 %0, %1, %2;" : "=r"(d) : "r"(a), "r"(b));
    return d;
}

// bit-select: (x & m) | (y & ~m)   -> single LOP3
__device__ __forceinline__ uint32_t bsel(uint32_t x, uint32_t y, uint32_t m) {
    return (x & m) | (y & ~m);
}

// sign-extend bit b of x to full word (0 or 0xFFFFFFFF) -> single BFE
__device__ __forceinline__ uint32_t bfe_s(uint32_t x, int b) {
    uint32_t r;
    asm("bfe.s32 %0, %1, %2, 1;" : "=r"(r) : "r"(x), "r"(b));
    return r;
}

// splice low halves: {a.b0, a.b1, b.b0, b.b1} -> halfword masks
__device__ __forceinline__ uint32_t prmt5410(uint32_t a, uint32_t b) {
    uint32_t r;
    asm("prmt.b32 %0, %1, %2, 0x5410;" : "=r"(r) : "r"(a), "r"(b));
    return r;
}

__device__ __forceinline__ float f4c(const float4& v, int k) {
    return k == 0 ? v.x : (k == 1 ? v.y : (k == 2 ? v.z : v.w));
}

// ---------------------------------------------------------------------------
// Kernel A (validated R14): no dynamic smem; 32KB static for W -> 3 CTAs/SM.
//   blocks [0,128): Wh = h @ W + packed attention tables (h via __ldg).
//   blocks [128, 1024): adj -> bitmask compression (2 granules per int4 step).
// ---------------------------------------------------------------------------
__global__ void __launch_bounds__(256, 3) wh_mask_kernel(const float* __restrict__ h,
                                                         const float* __restrict__ W,
                                                         const float* __restrict__ a,
                                                         const int* __restrict__ adj) {
    __shared__ float4 sW4[FI * FO / 4];   // 32 KB static

    if (blockIdx.x >= WH_BLOCKS) {
        const int lane = threadIdx.x & 31;
        const int gw = (blockIdx.x - WH_BLOCKS) * 8 + (threadIdx.x >> 5);
        for (int base = gw * 16; base < RC; base += MASK_WARPS * 16) {
            int4 v[8];
            #pragma unroll
            for (int u = 0; u < 8; ++u)
                v[u] = *(const int4*)(adj + (size_t)(base + 2 * u) * 64 + lane * 4);
            #pragma unroll
            for (int u = 0; u < 8; ++u) {
                const uint32_t m0 = __ballot_sync(0xffffffffu, v[u].x);
                const uint32_t m1 = __ballot_sync(0xffffffffu, v[u].y);
                const uint32_t m2 = __ballot_sync(0xffffffffu, v[u].z);
                const uint32_t m3 = __ballot_sync(0xffffffffu, v[u].w);
                if (lane == 0)
                    g_adjbits[base + 2 * u] = make_uint4(m0 & 0xFFFFu, m1 & 0xFFFFu,
                                                         m2 & 0xFFFFu, m3 & 0xFFFFu);
                else if (lane == 1)
                    g_adjbits[base + 2 * u + 1] = make_uint4(m0 >> 16, m1 >> 16,
                                                             m2 >> 16, m3 >> 16);
            }
        }
        return;
    }

    // ---------------- Wh blocks: W in smem, h via __ldg (L1-resident) -------
    const int tid  = threadIdx.x;
    const int row0 = blockIdx.x * 128;

    const float4* wsrc = (const float4*)W;
    #pragma unroll 2
    for (int i = tid; i < FI * FO / 4; i += 256) sW4[i] = wsrc[i];
    __syncthreads();

    const int fg   = tid & 7;
    const int rowg = tid >> 3;
    const float4* hrow = (const float4*)(h + (size_t)(row0 + rowg * 4) * FI);

    float acc[4][8];
    #pragma unroll
    for (int r = 0; r < 4; ++r)
        #pragma unroll
        for (int c = 0; c < 8; ++c) acc[r][c] = 0.f;

    #pragma unroll 2
    for (int k4 = 0; k4 < FI / 4; ++k4) {
        float4 hv[4];
        #pragma unroll
        for (int r = 0; r < 4; ++r) hv[r] = __ldg(hrow + r * (FI / 4) + k4);
        #pragma unroll
        for (int kk = 0; kk < 4; ++kk) {
            const float4 wa = sW4[(k4 * 4 + kk) * 16 + fg * 2];
            const float4 wb = sW4[(k4 * 4 + kk) * 16 + fg * 2 + 1];
            #pragma unroll
            for (int r = 0; r < 4; ++r) {
                const float hk = f4c(hv[r], kk);
                acc[r][0] = fmaf(hk, wa.x, acc[r][0]);
                acc[r][1] = fmaf(hk, wa.y, acc[r][1]);
                acc[r][2] = fmaf(hk, wa.z, acc[r][2]);
                acc[r][3] = fmaf(hk, wa.w, acc[r][3]);
                acc[r][4] = fmaf(hk, wb.x, acc[r][4]);
                acc[r][5] = fmaf(hk, wb.y, acc[r][5]);
                acc[r][6] = fmaf(hk, wb.z, acc[r][6]);
                acc[r][7] = fmaf(hk, wb.w, acc[r][7]);
            }
        }
    }

    const float4* a4 = (const float4*)a;
    const float4 a1a = a4[fg * 2], a1b = a4[fg * 2 + 1];
    const float4 a2a = a4[16 + fg * 2], a2b = a4[16 + fg * 2 + 1];
    float s1p[4], s2p[4];
    #pragma unroll
    for (int r = 0; r < 4; ++r) {
        s1p[r] = acc[r][0] * a1a.x + acc[r][1] * a1a.y + acc[r][2] * a1a.z + acc[r][3] * a1a.w
               + acc[r][4] * a1b.x + acc[r][5] * a1b.y + acc[r][6] * a1b.z + acc[r][7] * a1b.w;
        s2p[r] = acc[r][0] * a2a.x + acc[r][1] * a2a.y + acc[r][2] * a2a.z + acc[r][3] * a2a.w
               + acc[r][4] * a2b.x + acc[r][5] * a2b.y + acc[r][6] * a2b.z + acc[r][7] * a2b.w;
    }
    #pragma unroll
    for (int off = 1; off < 8; off <<= 1)
        #pragma unroll
        for (int r = 0; r < 4; ++r) {
            s1p[r] += __shfl_xor_sync(0xffffffffu, s1p[r], off);
            s2p[r] += __shfl_xor_sync(0xffffffffu, s2p[r], off);
        }
    if (fg == 0) {
        float e2v[4], f2v[4];
        const int base = row0 + rowg * 4;
        #pragma unroll
        for (int r = 0; r < 4; ++r) {
            const float s1 = s1p[r], s2 = s2p[r];
            const float e1 = __expf(s1), f1 = __expf(0.2f * s1);
            g_srowP[base + r] = make_uint4(h2u(-s1, -s1), h2u(e1, e1), h2u(f1, f1), 0u);
            e2v[r] = __expf(s2);
            f2v[r] = __expf(0.2f * s2);
        }
        #pragma unroll
        for (int pr = 0; pr < 2; ++pr) {
            g_scolP[(base >> 1) + pr] = make_uint4(
                h2u(s2p[pr * 2], s2p[pr * 2 + 1]),
                h2u(e2v[pr * 2], e2v[pr * 2 + 1]),
                h2u(f2v[pr * 2], f2v[pr * 2 + 1]), 0u);
        }
    }

    #pragma unroll
    for (int r = 0; r < 4; ++r) {
        const int row = row0 + rowg * 4 + r;
        uint32_t hw[4];
        #pragma unroll
        for (int cp = 0; cp < 4; ++cp)
            hw[cp] = h2u(acc[r][cp * 2], acc[r][cp * 2 + 1]);
        *(uint4*)(g_Wh_h + (size_t)row * FO + fg * 8) = make_uint4(hw[0], hw[1], hw[2], hw[3]);
    }
}

// ---------------------------------------------------------------------------
// Kernel 2: fused GAT attention, KT=128 chunks (16 total), 4-STAGE cp.async
// pipeline (one barrier per chunk is SAFE only at >=4 stages: fast warp in
// iter t stages (t+2)%4 which differs from laggard's read buf (t-1)%4).
// Warp (rowgroup, khalf): khalf = j-half of the 128-j chunk. adj via one
// uint4 mask per warp per chunk. Denominator via ones-column (col 64) MMA.
// ---------------------------------------------------------------------------
#define SB_STRIDE 144            // 72 fp16 cols: 64 data + col64=1.0 + zeros
#define SB_PLANE  (KT * SB_STRIDE)          // 18432
#define NSTAGE 4
#define OFF_SB    16384                         // after 16KB scolp
#define GAT_SMEM  (OFF_SB + NSTAGE * SB_PLANE)  // 90112
#define ACC_STRIDE 76            // 9 blocks*8 + den + pad

__device__ __forceinline__ void stage_chunk(uint32_t swh, int buf, int rowbase, int tid) {
    const uint32_t wbase = swh + buf * SB_PLANE;
    #pragma unroll
    for (int q = 0; q < 4; ++q) {
        const int id  = tid + q * 256;     // 0..1023
        const int row = id >> 3;
        const int c16 = id & 7;
        const __half* src = g_Wh_h + (size_t)(rowbase + row) * FO + c16 * 8;
        cpasync16(wbase + row * SB_STRIDE + c16 * 16, src);
    }
}

__global__ void __launch_bounds__(256, 2) gat_kernel(const int* __restrict__ adj,
                                                     float* __restrict__ out) {
    extern __shared__ __align__(16) unsigned char smem_raw[];
    uint4* scolp = (uint4*)smem_raw;                        // 16KB (per j-pair)
    float* accbuf = (float*)(smem_raw + OFF_SB);            // reuses staging
    const uint32_t swh = smem_u32(smem_raw) + OFF_SB;

    const int tid  = threadIdx.x;
    const int lane = tid & 31;
    const int wid  = tid >> 5;
    const int b    = blockIdx.y;
    const int i0   = blockIdx.x * TI;

    const int mb    = (wid & 3) * 16;   // warp row base (local, 0..48)
    const int khalf = wid >> 2;         // j-half of each 128-chunk
    const int lrl = mb + (lane >> 2);   // local row (lo)
    const int lrh = lrl + 8;
    const int qc  = (lane & 3) * 2;     // k-pair base within 16

    // preload packed scol pairs for batch b (16KB)
    {
        const uint4* src = g_scolP + b * (NN / 2);
        #pragma unroll 2
        for (int i = tid; i < NN / 2; i += 256) scolp[i] = src[i];
    }
    // one-time init: pad cols 64-71 -> (1.0h, 0...) in all stage buffers
    for (int id = tid; id < NSTAGE * KT; id += 256) {
        const int s = id / KT, row = id % KT;
        *(uint4*)(smem_raw + OFF_SB + s * SB_PLANE + row * SB_STRIDE + 128) =
            make_uint4(0x3C00u, 0u, 0u, 0u);
    }

    const uint4 rplo = g_srowP[b * NN + i0 + lrl];
    const uint4 rphi = g_srowP[b * NN + i0 + lrh];
    const uint4* abl = g_adjbits + (size_t)(b * NN + i0 + lrl) * (NN / 64);
    const uint4* abh = g_adjbits + (size_t)(b * NN + i0 + lrh) * (NN / 64);

    stage_chunk(swh, 0, b * NN, tid);
    asm volatile("cp.async.commit_group;" ::: "memory");
    stage_chunk(swh, 1, b * NN + KT, tid);
    asm volatile("cp.async.commit_group;" ::: "memory");

    uint4 mcl = abl[khalf], mch = abh[khalf];     // masks for chunk 0 (this half)
    __syncthreads();   // scolp + pad init visible

    float acc[9][4];   // blocks 0-7: cols 0-63; block 8: den (col 64)
    #pragma unroll
    for (int nt = 0; nt < 9; ++nt)
        #pragma unroll
        for (int k = 0; k < 4; ++k) acc[nt][k] = 0.f;

    const int lrow = (lane & 7) + (lane & 8);       // ldmatrix x4 row 0..15
    const int lcol = (lane >> 4) << 3;              // 0 or 8
    const int drow = lane & 15;                     // ldmatrix x2 row
    const int kq   = lane & 3;                      // pair sub-index
    const int kodd = kq & 1;                        // which mask words
    const int bq   = kq >> 1;                       // sub-bit within slice

    #pragma unroll 1
    for (int t = 0; t < NCHUNK; ++t) {
        uint4 mnl, mnh;
        if (t + 1 < NCHUNK) {
            mnl = abl[2 * (t + 1) + khalf];
            mnh = abh[2 * (t + 1) + khalf];
        }
        if (t + 2 < NCHUNK) {
            stage_chunk(swh, (t + 2) % NSTAGE, b * NN + (t + 2) * KT, tid);
            asm volatile("cp.async.commit_group;" ::: "memory");
            asm volatile("cp.async.wait_group 2;" ::: "memory");
        } else if (t + 1 < NCHUNK) {
            asm volatile("cp.async.wait_group 1;" ::: "memory");
        } else {
            asm volatile("cp.async.wait_group 0;" ::: "memory");
        }
        __syncthreads();   // chunk t landed; single barrier per chunk

        const uint32_t bufh = swh + (t % NSTAGE) * SB_PLANE;

        // mask words for this thread's pair parity (2 SELs per row)
        const uint32_t ual = kodd ? mcl.z : mcl.x;
        const uint32_t uvl = kodd ? mcl.w : mcl.y;
        const uint32_t uah = kodd ? mch.z : mch.x;
        const uint32_t uvh = kodd ? mch.w : mch.y;

        #pragma unroll
        for (int kt2 = 0; kt2 < 4; ++kt2) {
            const int ktg = khalf * 4 + kt2;          // slice within 128-chunk
            const int jp  = t * 64 + khalf * 32 + kt2 * 8 + kq;   // global j-pair
            const int bit = kt2 * 4 + bq;             // mask bit for c01
            const uint4 c01 = scolp[jp];
            const uint4 c89 = scolp[jp + 4];

            // A fragments: p = bitsel(E,F, s2>-s1) pairwise, masked by adj bits
            uint32_t m;
            m = setgt2(c01.x, rplo.x);
            const uint32_t a0 = hmul2u(bsel(rplo.y, rplo.z, m), bsel(c01.y, c01.z, m))
                                & prmt5410(bfe_s(ual, bit), bfe_s(uvl, bit));
            m = setgt2(c01.x, rphi.x);
            const uint32_t a1 = hmul2u(bsel(rphi.y, rphi.z, m), bsel(c01.y, c01.z, m))
                                & prmt5410(bfe_s(uah, bit), bfe_s(uvh, bit));
            m = setgt2(c89.x, rplo.x);
            const uint32_t a2 = hmul2u(bsel(rplo.y, rplo.z, m), bsel(c89.y, c89.z, m))
                                & prmt5410(bfe_s(ual, bit + 2), bfe_s(uvl, bit + 2));
            m = setgt2(c89.x, rphi.x);
            const uint32_t a3 = hmul2u(bsel(rphi.y, rphi.z, m), bsel(c89.y, c89.z, m))
                                & prmt5410(bfe_s(uah, bit + 2), bfe_s(uvh, bit + 2));

            // B fragments: 64 data cols + ones column (den)
            const uint32_t rowoff = (uint32_t)(ktg * 16 + lrow) * SB_STRIDE + lcol * 2;
            #pragma unroll
            for (int ci = 0; ci < 4; ++ci) {
                uint32_t bt[4];
                ldsm4t(bt, bufh + rowoff + ci * 32);
                mma16816(acc[ci * 2 + 0], a0, a1, a2, a3, bt[0], bt[1]);
                mma16816(acc[ci * 2 + 1], a0, a1, a2, a3, bt[2], bt[3]);
            }
            uint32_t dt[2];
            ldsm2t(dt, bufh + (uint32_t)(ktg * 16 + drow) * SB_STRIDE + 128);
            mma16816(acc[8], a0, a1, a2, a3, dt[0], dt[1]);
        }
        mcl = mnl; mch = mnh;
        // no trailing barrier: at 4 stages, staging (t+2)%4 never collides
        // with a laggard reading (t-1)%4
    }

    __syncthreads();   // staging region now reusable for the acc exchange

    // ---- merge across khalf: khalf=1 publishes partials
    if (khalf) {
        #pragma unroll
        for (int nt = 0; nt < 8; ++nt) {
            *(float2*)(accbuf + lrl * ACC_STRIDE + nt * 8 + qc) =
                make_float2(acc[nt][0], acc[nt][1]);
            *(float2*)(accbuf + lrh * ACC_STRIDE + nt * 8 + qc) =
                make_float2(acc[nt][2], acc[nt][3]);
        }
        if ((lane & 3) == 0) {
            accbuf[lrl * ACC_STRIDE + 72] = acc[8][0];
            accbuf[lrh * ACC_STRIDE + 72] = acc[8][2];
        }
    }
    __syncthreads();

    if (!khalf) {
        float invl = 0.f, invh = 0.f;
        if ((lane & 3) == 0) {
            invl = 1.0f / (acc[8][0] + accbuf[lrl * ACC_STRIDE + 72]);
            invh = 1.0f / (acc[8][2] + accbuf[lrh * ACC_STRIDE + 72]);
        }
        invl = __shfl_sync(0xffffffffu, invl, lane & ~3);
        invh = __shfl_sync(0xffffffffu, invh, lane & ~3);
        float* outl = out + (size_t)(b * NN + i0 + lrl) * FO;
        float* outh = out + (size_t)(b * NN + i0 + lrh) * FO;
        #pragma unroll
        for (int nt = 0; nt < 8; ++nt) {
            const int cb = nt * 8 + qc;
            const float2 tl = *(const float2*)(accbuf + lrl * ACC_STRIDE + cb);
            const float2 th = *(const float2*)(accbuf + lrh * ACC_STRIDE + cb);
            float2 o;
            float v;
            v = (acc[nt][0] + tl.x) * invl; o.x = (v > 0.f) ? v : expm1f(v);
            v = (acc[nt][1] + tl.y) * invl; o.y = (v > 0.f) ? v : expm1f(v);
            *(float2*)(outl + cb) = o;
            v = (acc[nt][2] + th.x) * invh; o.x = (v > 0.f) ? v : expm1f(v);
            v = (acc[nt][3] + th.y) * invh; o.y = (v > 0.f) ? v : expm1f(v);
            *(float2*)(outh + cb) = o;
        }
    }
}

// ---------------------------------------------------------------------------
extern "C" void kernel_launch(void* const* d_in, const int* in_sizes, int n_in,
                              void* d_out, int out_size) {
    const float* h   = (const float*)d_in[0];   // [8,2048,128] f32
    const float* W   = (const float*)d_in[1];   // [128,64] f32
    const float* a   = (const float*)d_in[2];   // [128,1] f32
    const int*   adj = (const int*)d_in[3];     // [8,2048,2048] i32
    float* out = (float*)d_out;                 // [8,2048,64] f32

    cudaFuncSetAttribute(gat_kernel, cudaFuncAttributeMaxDynamicSharedMemorySize, GAT_SMEM);

    wh_mask_kernel<<<WH_BLOCKS + MASK_BLOCKS, 256>>>(h, W, a, adj);
    dim3 grid(NN / TI, BB);
    gat_kernel<<<grid, 256, GAT_SMEM>>>(adj, out);
}